// round 7
// baseline (speedup 1.0000x reference)
#include <cuda_runtime.h>
#include <math.h>

#define TT 8
#define NI 20000
#define NK 50000
#define FF 128
#define HH 256
#define OO 128
#define EE 500000
#define MAXS 512

// ---------------- scratch (device globals; no allocation allowed) ----------------
__device__ int   g_item_flag[TT][NK];     // -1 empty, -2 marked, >=0 slot
__device__ int   g_item_mult[TT][NK];     // edge multiplicity (src,target) in e2
__device__ int   g_item_id[TT][MAXS];
__device__ int   g_item_cnt[TT][MAXS];    // e1 in-degree of needed item
__device__ float g_item_acc[TT][MAXS][FF];
__device__ float g_hitem[TT][MAXS][HH];
__device__ int   g_num_items[TT];
__device__ float g_accx[TT][FF];          // sum of x_item over target's e2 edges
__device__ int   g_edge_cnt[TT];
__device__ float g_gi[TT][3 * HH];
__device__ float g_hbuf[2][HH];
__device__ float g_rnn[TT][HH];

// ---------------- init / reset (R1-proven) ----------------
__global__ void k_init() {
    int idx = blockIdx.x * blockDim.x + threadIdx.x;
    if (idx < TT * NK) {
        ((int*)g_item_flag)[idx] = -1;
        ((int*)g_item_mult)[idx] = 0;
    }
    if (idx < TT * MAXS * FF) ((float*)g_item_acc)[idx] = 0.0f;
    if (idx < TT * MAXS)      ((int*)g_item_cnt)[idx] = 0;
    if (idx < TT * FF)        ((float*)g_accx)[idx] = 0.0f;
    if (idx < TT) { g_edge_cnt[idx] = 0; g_num_items[idx] = 0; }
    if (idx < 2 * HH) ((float*)g_hbuf)[idx] = 0.0f;
}

// ---------------- pass A: scan e2 (R1-proven) ----------------
__global__ void k_scan_e2(const int* __restrict__ e2s, const int* __restrict__ e2d,
                          const float* __restrict__ x_item, const int* __restrict__ tgtp) {
    int t = blockIdx.y;
    int tgt = *tgtp;
    const int* d = e2d + (size_t)t * EE;
    const int* s = e2s + (size_t)t * EE;
    for (int e = blockIdx.x * blockDim.x + threadIdx.x; e < EE; e += gridDim.x * blockDim.x) {
        if (d[e] == tgt) {
            int src = s[e];
            atomicAdd(&g_edge_cnt[t], 1);
            atomicAdd(&g_item_mult[t][src], 1);
            int old = atomicExch(&g_item_flag[t][src], -2);
            if (old == -1) {
                int sl = atomicAdd(&g_num_items[t], 1);
                if (sl < MAXS) g_item_id[t][sl] = src;
            }
            const float* xr = x_item + ((size_t)t * NK + src) * FF;
            #pragma unroll 4
            for (int f = 0; f < FF; f++) atomicAdd(&g_accx[t][f], xr[f]);
        }
    }
}

// ---------------- pass A2: assign slot ids (R1-proven) ----------------
__global__ void k_assign() {
    int t = blockIdx.x;
    if (threadIdx.x == 0 && g_num_items[t] > MAXS) g_num_items[t] = MAXS;
    __syncthreads();
    int n = g_num_items[t];
    for (int k = threadIdx.x; k < n; k += blockDim.x)
        g_item_flag[t][g_item_id[t][k]] = k;
}

// ---------------- pass B: scan e1 (R1-proven) ----------------
__global__ void k_scan_e1(const int* __restrict__ e1s, const int* __restrict__ e1d,
                          const float* __restrict__ x_inf) {
    int t = blockIdx.y;
    const int* d = e1d + (size_t)t * EE;
    const int* s = e1s + (size_t)t * EE;
    for (int e = blockIdx.x * blockDim.x + threadIdx.x; e < EE; e += gridDim.x * blockDim.x) {
        int dst = d[e];
        int sl = g_item_flag[t][dst];
        if (sl >= 0) {
            atomicAdd(&g_item_cnt[t][sl], 1);
            int src = s[e];
            const float* xr = x_inf + ((size_t)t * NI + src) * FF;
            #pragma unroll 4
            for (int f = 0; f < FF; f++) atomicAdd(&g_item_acc[t][sl][f], xr[f]);
        }
    }
}

// ---------------- fused per-t: h_item slots + o_inf[target] + GRU input gates ----------------
// (directly profiled at 1.3us in R2/R3 captures)
__global__ void k_pert(const float* __restrict__ x_item, const float* __restrict__ x_inf,
                       const float* __restrict__ W1a_l, const float* __restrict__ b1a_l,
                       const float* __restrict__ W1a_r,
                       const float* __restrict__ W1b_l, const float* __restrict__ b1b_l,
                       const float* __restrict__ W1b_r,
                       const float* __restrict__ W2b_l, const float* __restrict__ b2b_l,
                       const float* __restrict__ W2b_r,
                       const float* __restrict__ W_ih, const float* __restrict__ b_ih,
                       const int* __restrict__ tgtp) {
    int t = blockIdx.x;
    int tid = threadIdx.x;
    __shared__ float mean[FF], xrow[FF], hinf[HH], meanh[HH], multw[MAXS], xs[OO];
    int n = g_num_items[t];
    if (n > MAXS) n = MAXS;

    // --- h_item for each needed slot ---
    for (int sl = 0; sl < n; sl++) {
        if (tid < FF) {
            float c = fmaxf((float)g_item_cnt[t][sl], 1.0f);
            mean[tid] = g_item_acc[t][sl][tid] / c;
            xrow[tid] = x_item[((size_t)t * NK + g_item_id[t][sl]) * FF + tid];
        }
        __syncthreads();
        int h = tid;
        float a = b1a_l[h];
        const float* wl = W1a_l + (size_t)h * FF;
        const float* wr = W1a_r + (size_t)h * FF;
        #pragma unroll 8
        for (int f = 0; f < FF; f++) a += mean[f] * wl[f] + xrow[f] * wr[f];
        g_hitem[t][sl][h] = fmaxf(a, 0.0f);
        __syncthreads();
    }

    // --- h_inf[target] + weighted mean of h_item over target's e2 edges ---
    int tgt = *tgtp;
    float ec = fmaxf((float)g_edge_cnt[t], 1.0f);
    if (tid < FF) {
        mean[tid] = g_accx[t][tid] / ec;
        xrow[tid] = x_inf[((size_t)t * NI + tgt) * FF + tid];
    }
    for (int k = tid; k < n; k += blockDim.x)
        multw[k] = (float)g_item_mult[t][g_item_id[t][k]];
    __syncthreads();
    {
        int h = tid;
        float v = b1b_l[h];
        const float* wl = W1b_l + (size_t)h * FF;
        const float* wr = W1b_r + (size_t)h * FF;
        #pragma unroll 8
        for (int f = 0; f < FF; f++) v += mean[f] * wl[f] + xrow[f] * wr[f];
        hinf[h] = fmaxf(v, 0.0f);
        float mh = 0.0f;
        for (int k = 0; k < n; k++) mh += multw[k] * g_hitem[t][k][h];
        meanh[h] = mh / ec;
    }
    __syncthreads();

    // --- o_inf[target] -> xs ---
    if (tid < OO) {
        int o = tid;
        float v = b2b_l[o];
        const float* wl = W2b_l + (size_t)o * HH;
        const float* wr = W2b_r + (size_t)o * HH;
        #pragma unroll 8
        for (int h2 = 0; h2 < HH; h2++) v += meanh[h2] * wl[h2] + hinf[h2] * wr[h2];
        xs[o] = v;
    }
    __syncthreads();

    // --- GRU input gates gi = W_ih @ seq[t] + b_ih ---
    for (int row = tid; row < 3 * HH; row += blockDim.x) {
        float v = b_ih[row];
        const float* w = W_ih + (size_t)row * OO;
        #pragma unroll 8
        for (int o = 0; o < OO; o++) v += w[o] * xs[o];
        g_gi[t][row] = v;
    }
}

// ---------------- one GRU step: warp per h-row (R1-proven, coalesced) ----------------
__global__ void k_gru(int t, const float* __restrict__ W_hh, const float* __restrict__ b_hh) {
    const float* hprev = g_hbuf[t & 1];
    float* hnext = g_hbuf[(t + 1) & 1];
    int gwarp = (blockIdx.x * blockDim.x + threadIdx.x) >> 5;
    int lane = threadIdx.x & 31;
    if (gwarp >= HH) return;
    int w = gwarp;
    float sr = 0.0f, sz = 0.0f, sn = 0.0f;
    const float* wr = W_hh + (size_t)w * HH;
    const float* wz = W_hh + (size_t)(HH + w) * HH;
    const float* wn = W_hh + (size_t)(2 * HH + w) * HH;
    #pragma unroll
    for (int j = 0; j < HH / 32; j++) {
        int k = lane + 32 * j;
        float hv = hprev[k];
        sr += wr[k] * hv;
        sz += wz[k] * hv;
        sn += wn[k] * hv;
    }
    #pragma unroll
    for (int off = 16; off > 0; off >>= 1) {
        sr += __shfl_down_sync(0xffffffffu, sr, off);
        sz += __shfl_down_sync(0xffffffffu, sz, off);
        sn += __shfl_down_sync(0xffffffffu, sn, off);
    }
    if (lane == 0) {
        float gh_r = sr + b_hh[w];
        float gh_z = sz + b_hh[HH + w];
        float gh_n = sn + b_hh[2 * HH + w];
        float gi_r = g_gi[t][w];
        float gi_z = g_gi[t][HH + w];
        float gi_n = g_gi[t][2 * HH + w];
        float r = 1.0f / (1.0f + expf(-(gi_r + gh_r)));
        float z = 1.0f / (1.0f + expf(-(gi_z + gh_z)));
        float nn = tanhf(gi_n + r * gh_n);
        float hn = (1.0f - z) * nn + z * hprev[w];
        hnext[w] = hn;
        g_rnn[t][w] = hn;
    }
}

// ---------------- attention + prediction head (R1-proven) ----------------
__global__ void k_head(const float* __restrict__ W_att, const float* __restrict__ b_att,
                       const float* __restrict__ W_p1, const float* __restrict__ b_p1,
                       const float* __restrict__ W_p2, const float* __restrict__ b_p2,
                       float* __restrict__ out) {
    __shared__ float att[TT], ctx[HH], red[HH];
    int tid = threadIdx.x;
    if (tid < TT) {
        float lg = b_att[0];
        for (int h = 0; h < HH; h++) lg += g_rnn[tid][h] * W_att[h];
        att[tid] = lg;
    }
    __syncthreads();
    if (tid == 0) {
        float m = att[0];
        for (int t = 1; t < TT; t++) m = fmaxf(m, att[t]);
        float s = 0.0f;
        for (int t = 0; t < TT; t++) { att[t] = expf(att[t] - m); s += att[t]; }
        for (int t = 0; t < TT; t++) att[t] /= s;
    }
    __syncthreads();
    {
        float c = 0.0f;
        #pragma unroll
        for (int t = 0; t < TT; t++) c += att[t] * g_rnn[t][tid];
        ctx[tid] = c;
    }
    __syncthreads();
    if (tid < HH / 2) {
        float v = b_p1[tid];
        const float* w = W_p1 + (size_t)tid * HH;
        #pragma unroll 8
        for (int h = 0; h < HH; h++) v += w[h] * ctx[h];
        v = fmaxf(v, 0.0f);
        red[tid] = v * W_p2[tid];
    }
    __syncthreads();
    if (tid == 0) {
        float s = b_p2[0];
        for (int j = 0; j < HH / 2; j++) s += red[j];
        out[0] = s;
    }
}

extern "C" void kernel_launch(void* const* d_in, const int* in_sizes, int n_in,
                              void* d_out, int out_size) {
    const float* x_inf  = (const float*)d_in[0];
    const float* x_item = (const float*)d_in[1];
    const int*   e1s    = (const int*)d_in[2];
    const int*   e1d    = (const int*)d_in[3];
    const int*   e2s    = (const int*)d_in[4];
    const int*   e2d    = (const int*)d_in[5];
    const int*   tgt    = (const int*)d_in[6];
    const float* W1a_l  = (const float*)d_in[7];
    const float* b1a_l  = (const float*)d_in[8];
    const float* W1a_r  = (const float*)d_in[9];
    const float* W1b_l  = (const float*)d_in[10];
    const float* b1b_l  = (const float*)d_in[11];
    const float* W1b_r  = (const float*)d_in[12];
    // d_in[13..15]: W2a_* (dead code in reference — o_item unused)
    const float* W2b_l  = (const float*)d_in[16];
    const float* b2b_l  = (const float*)d_in[17];
    const float* W2b_r  = (const float*)d_in[18];
    const float* W_ih   = (const float*)d_in[19];
    const float* W_hh   = (const float*)d_in[20];
    const float* b_ih   = (const float*)d_in[21];
    const float* b_hh   = (const float*)d_in[22];
    const float* W_att  = (const float*)d_in[23];
    const float* b_att  = (const float*)d_in[24];
    const float* W_p1   = (const float*)d_in[25];
    const float* b_p1   = (const float*)d_in[26];
    const float* W_p2   = (const float*)d_in[27];
    const float* b_p2   = (const float*)d_in[28];
    float* out = (float*)d_out;

    k_init<<<2048, 256>>>();
    dim3 gscan(512, TT);
    k_scan_e2<<<gscan, 256>>>(e2s, e2d, x_item, tgt);
    k_assign<<<TT, 256>>>();
    k_scan_e1<<<gscan, 256>>>(e1s, e1d, x_inf);
    k_pert<<<TT, 256>>>(x_item, x_inf, W1a_l, b1a_l, W1a_r, W1b_l, b1b_l, W1b_r,
                        W2b_l, b2b_l, W2b_r, W_ih, b_ih, tgt);
    for (int t = 0; t < TT; t++)
        k_gru<<<32, 256>>>(t, W_hh, b_hh);
    k_head<<<1, 256>>>(W_att, b_att, W_p1, b_p1, W_p2, b_p2, out);
}

// round 8
// speedup vs baseline: 11.6038x; 11.6038x over previous
#include <cuda_runtime.h>
#include <math.h>

#define TT 8
#define NI 20000
#define NK 50000
#define FF 128
#define HH 256
#define OO 128
#define EE 500000
#define MAXS 512

// ---------------- scratch (device globals; no allocation allowed) ----------------
__device__ int   g_item_flag[TT][NK];     // -1 empty, -2 marked, >=0 slot
__device__ int   g_item_mult[TT][NK];     // edge multiplicity (src,target) in e2
__device__ int   g_item_id[TT][MAXS];
__device__ int   g_item_cnt[TT][MAXS];    // e1 in-degree of needed item
__device__ float g_item_acc[TT][MAXS][FF];
__device__ float g_hitem[TT][MAXS][HH];
__device__ int   g_num_items[TT];
__device__ float g_accx[TT][FF];          // sum of x_item over target's e2 edges
__device__ int   g_edge_cnt[TT];
__device__ float g_seq[TT][OO];
__device__ float g_gi[TT][3 * HH];
__device__ float g_hbuf[2][HH];
__device__ float g_rnn[TT][HH];

// ---------------- init / reset (R1-proven) ----------------
__global__ void k_init() {
    int idx = blockIdx.x * blockDim.x + threadIdx.x;
    if (idx < TT * NK) {
        ((int*)g_item_flag)[idx] = -1;
        ((int*)g_item_mult)[idx] = 0;
    }
    if (idx < TT * MAXS * FF) ((float*)g_item_acc)[idx] = 0.0f;
    if (idx < TT * MAXS)      ((int*)g_item_cnt)[idx] = 0;
    if (idx < TT * FF)        ((float*)g_accx)[idx] = 0.0f;
    if (idx < TT) { g_edge_cnt[idx] = 0; g_num_items[idx] = 0; }
    if (idx < 2 * HH) ((float*)g_hbuf)[idx] = 0.0f;
}

// ---------------- pass A: scan e2 (R1-proven, untouched) ----------------
__global__ void k_scan_e2(const int* __restrict__ e2s, const int* __restrict__ e2d,
                          const float* __restrict__ x_item, const int* __restrict__ tgtp) {
    int t = blockIdx.y;
    int tgt = *tgtp;
    const int* d = e2d + (size_t)t * EE;
    const int* s = e2s + (size_t)t * EE;
    for (int e = blockIdx.x * blockDim.x + threadIdx.x; e < EE; e += gridDim.x * blockDim.x) {
        if (d[e] == tgt) {
            int src = s[e];
            atomicAdd(&g_edge_cnt[t], 1);
            atomicAdd(&g_item_mult[t][src], 1);
            int old = atomicExch(&g_item_flag[t][src], -2);
            if (old == -1) {
                int sl = atomicAdd(&g_num_items[t], 1);
                if (sl < MAXS) g_item_id[t][sl] = src;
            }
            const float* xr = x_item + ((size_t)t * NK + src) * FF;
            #pragma unroll 4
            for (int f = 0; f < FF; f++) atomicAdd(&g_accx[t][f], xr[f]);
        }
    }
}

// ---------------- pass A2: assign slot ids (R1-proven, untouched) ----------------
__global__ void k_assign() {
    int t = blockIdx.x;
    if (threadIdx.x == 0 && g_num_items[t] > MAXS) g_num_items[t] = MAXS;
    __syncthreads();
    int n = g_num_items[t];
    for (int k = threadIdx.x; k < n; k += blockDim.x)
        g_item_flag[t][g_item_id[t][k]] = k;
}

// ---------------- pass B: scan e1 (R1-proven, untouched) ----------------
__global__ void k_scan_e1(const int* __restrict__ e1s, const int* __restrict__ e1d,
                          const float* __restrict__ x_inf) {
    int t = blockIdx.y;
    const int* d = e1d + (size_t)t * EE;
    const int* s = e1s + (size_t)t * EE;
    for (int e = blockIdx.x * blockDim.x + threadIdx.x; e < EE; e += gridDim.x * blockDim.x) {
        int dst = d[e];
        int sl = g_item_flag[t][dst];
        if (sl >= 0) {
            atomicAdd(&g_item_cnt[t][sl], 1);
            int src = s[e];
            const float* xr = x_inf + ((size_t)t * NI + src) * FF;
            #pragma unroll 4
            for (int f = 0; f < FF; f++) atomicAdd(&g_item_acc[t][sl][f], xr[f]);
        }
    }
}

__device__ __forceinline__ float warp_sum(float v) {
    #pragma unroll
    for (int off = 16; off > 0; off >>= 1) v += __shfl_down_sync(0xffffffffu, v, off);
    return v;
}

// ---------------- pass C: h_item, COALESCED warp-per-row ----------------
__global__ void k_hitem(const float* __restrict__ x_item,
                        const float* __restrict__ W1a_l, const float* __restrict__ b1a_l,
                        const float* __restrict__ W1a_r) {
    int t = blockIdx.y;
    int tid = threadIdx.x;
    int wid = tid >> 5, lane = tid & 31;
    __shared__ float4 mean4[FF / 4], xrow4[FF / 4];
    for (int sl = blockIdx.x; sl < g_num_items[t]; sl += gridDim.x) {
        int id = g_item_id[t][sl];
        float c = fmaxf((float)g_item_cnt[t][sl], 1.0f);
        if (tid < FF) {
            ((float*)mean4)[tid] = g_item_acc[t][sl][tid] / c;
            ((float*)xrow4)[tid] = x_item[((size_t)t * NK + id) * FF + tid];
        }
        __syncthreads();
        float4 m = mean4[lane], x = xrow4[lane];
        for (int h = wid; h < HH; h += 8) {
            float4 wl = ((const float4*)(W1a_l + (size_t)h * FF))[lane];
            float4 wr = ((const float4*)(W1a_r + (size_t)h * FF))[lane];
            float a = wl.x * m.x + wl.y * m.y + wl.z * m.z + wl.w * m.w
                    + wr.x * x.x + wr.y * x.y + wr.z * x.z + wr.w * x.w;
            a = warp_sum(a);
            if (lane == 0) g_hitem[t][sl][h] = fmaxf(a + b1a_l[h], 0.0f);
        }
        __syncthreads();
    }
}

// ---------------- pass D: h_inf[target] + o_inf[target], COALESCED ----------------
__global__ void k_oinf(const float* __restrict__ x_inf,
                       const float* __restrict__ W1b_l, const float* __restrict__ b1b_l,
                       const float* __restrict__ W1b_r,
                       const float* __restrict__ W2b_l, const float* __restrict__ b2b_l,
                       const float* __restrict__ W2b_r,
                       const int* __restrict__ tgtp) {
    int t = blockIdx.x;
    int tid = threadIdx.x;
    int wid = tid >> 5, lane = tid & 31;
    int tgt = *tgtp;
    __shared__ float4 meanx4[FF / 4], xt4[FF / 4];
    __shared__ float4 hinf4[HH / 4], meanh4[HH / 4];
    __shared__ float multw[MAXS];
    float ec = fmaxf((float)g_edge_cnt[t], 1.0f);
    int n = g_num_items[t];
    if (n > MAXS) n = MAXS;
    if (tid < FF) {
        ((float*)meanx4)[tid] = g_accx[t][tid] / ec;
        ((float*)xt4)[tid]    = x_inf[((size_t)t * NI + tgt) * FF + tid];
    }
    for (int k = tid; k < n; k += blockDim.x)
        multw[k] = (float)g_item_mult[t][g_item_id[t][k]];
    __syncthreads();

    // meanh[h]: coalesced across threads (consecutive h = consecutive floats)
    {
        float mh = 0.0f;
        for (int k = 0; k < n; k++) mh += multw[k] * g_hitem[t][k][tid];
        ((float*)meanh4)[tid] = mh / ec;
    }
    // hinf: warp-per-row over W1b (128-wide rows, one float4/lane)
    {
        float4 m = meanx4[lane], x = xt4[lane];
        for (int h = wid; h < HH; h += 8) {
            float4 wl = ((const float4*)(W1b_l + (size_t)h * FF))[lane];
            float4 wr = ((const float4*)(W1b_r + (size_t)h * FF))[lane];
            float a = wl.x * m.x + wl.y * m.y + wl.z * m.z + wl.w * m.w
                    + wr.x * x.x + wr.y * x.y + wr.z * x.z + wr.w * x.w;
            a = warp_sum(a);
            if (lane == 0) ((float*)hinf4)[h] = fmaxf(a + b1b_l[h], 0.0f);
        }
    }
    __syncthreads();

    // o_inf: warp-per-row over W2b (256-wide rows, two float4/lane)
    {
        float4 m0 = meanh4[lane], m1 = meanh4[lane + 32];
        float4 h0 = hinf4[lane],  h1 = hinf4[lane + 32];
        for (int o = wid; o < OO; o += 8) {
            const float4* wl = (const float4*)(W2b_l + (size_t)o * HH);
            const float4* wr = (const float4*)(W2b_r + (size_t)o * HH);
            float4 a0 = wl[lane], a1 = wl[lane + 32];
            float4 b0 = wr[lane], b1 = wr[lane + 32];
            float v = a0.x * m0.x + a0.y * m0.y + a0.z * m0.z + a0.w * m0.w
                    + a1.x * m1.x + a1.y * m1.y + a1.z * m1.z + a1.w * m1.w
                    + b0.x * h0.x + b0.y * h0.y + b0.z * h0.z + b0.w * h0.w
                    + b1.x * h1.x + b1.y * h1.y + b1.z * h1.z + b1.w * h1.w;
            v = warp_sum(v);
            if (lane == 0) g_seq[t][o] = v + b2b_l[o];
        }
    }
}

// ---------------- GRU input gates, COALESCED warp-per-row ----------------
__global__ void k_gi(const float* __restrict__ W_ih, const float* __restrict__ b_ih) {
    int t = blockIdx.y;
    int tid = threadIdx.x;
    int wid = tid >> 5, lane = tid & 31;
    __shared__ float4 xs4[OO / 4];
    if (tid < OO) ((float*)xs4)[tid] = g_seq[t][tid];
    __syncthreads();
    float4 x = xs4[lane];
    int gw = blockIdx.x * 8 + wid;           // 0..95 global warps
    for (int row = gw; row < 3 * HH; row += 96) {
        float4 w = ((const float4*)(W_ih + (size_t)row * OO))[lane];
        float v = w.x * x.x + w.y * x.y + w.z * x.z + w.w * x.w;
        v = warp_sum(v);
        if (lane == 0) g_gi[t][row] = v + b_ih[row];
    }
}

// ---------------- one GRU step: warp per h-row (R1-proven, untouched) ----------------
__global__ void k_gru(int t, const float* __restrict__ W_hh, const float* __restrict__ b_hh) {
    const float* hprev = g_hbuf[t & 1];
    float* hnext = g_hbuf[(t + 1) & 1];
    int gwarp = (blockIdx.x * blockDim.x + threadIdx.x) >> 5;
    int lane = threadIdx.x & 31;
    if (gwarp >= HH) return;
    int w = gwarp;
    float sr = 0.0f, sz = 0.0f, sn = 0.0f;
    const float* wr = W_hh + (size_t)w * HH;
    const float* wz = W_hh + (size_t)(HH + w) * HH;
    const float* wn = W_hh + (size_t)(2 * HH + w) * HH;
    #pragma unroll
    for (int j = 0; j < HH / 32; j++) {
        int k = lane + 32 * j;
        float hv = hprev[k];
        sr += wr[k] * hv;
        sz += wz[k] * hv;
        sn += wn[k] * hv;
    }
    #pragma unroll
    for (int off = 16; off > 0; off >>= 1) {
        sr += __shfl_down_sync(0xffffffffu, sr, off);
        sz += __shfl_down_sync(0xffffffffu, sz, off);
        sn += __shfl_down_sync(0xffffffffu, sn, off);
    }
    if (lane == 0) {
        float gh_r = sr + b_hh[w];
        float gh_z = sz + b_hh[HH + w];
        float gh_n = sn + b_hh[2 * HH + w];
        float gi_r = g_gi[t][w];
        float gi_z = g_gi[t][HH + w];
        float gi_n = g_gi[t][2 * HH + w];
        float r = 1.0f / (1.0f + expf(-(gi_r + gh_r)));
        float z = 1.0f / (1.0f + expf(-(gi_z + gh_z)));
        float nn = tanhf(gi_n + r * gh_n);
        float hn = (1.0f - z) * nn + z * hprev[w];
        hnext[w] = hn;
        g_rnn[t][w] = hn;
    }
}

// ---------------- attention + prediction head (R1-proven, untouched) ----------------
__global__ void k_head(const float* __restrict__ W_att, const float* __restrict__ b_att,
                       const float* __restrict__ W_p1, const float* __restrict__ b_p1,
                       const float* __restrict__ W_p2, const float* __restrict__ b_p2,
                       float* __restrict__ out) {
    __shared__ float att[TT], ctx[HH], red[HH];
    int tid = threadIdx.x;
    if (tid < TT) {
        float lg = b_att[0];
        for (int h = 0; h < HH; h++) lg += g_rnn[tid][h] * W_att[h];
        att[tid] = lg;
    }
    __syncthreads();
    if (tid == 0) {
        float m = att[0];
        for (int t = 1; t < TT; t++) m = fmaxf(m, att[t]);
        float s = 0.0f;
        for (int t = 0; t < TT; t++) { att[t] = expf(att[t] - m); s += att[t]; }
        for (int t = 0; t < TT; t++) att[t] /= s;
    }
    __syncthreads();
    {
        float c = 0.0f;
        #pragma unroll
        for (int t = 0; t < TT; t++) c += att[t] * g_rnn[t][tid];
        ctx[tid] = c;
    }
    __syncthreads();
    if (tid < HH / 2) {
        float v = b_p1[tid];
        const float* w = W_p1 + (size_t)tid * HH;
        #pragma unroll 8
        for (int h = 0; h < HH; h++) v += w[h] * ctx[h];
        v = fmaxf(v, 0.0f);
        red[tid] = v * W_p2[tid];
    }
    __syncthreads();
    if (tid == 0) {
        float s = b_p2[0];
        for (int j = 0; j < HH / 2; j++) s += red[j];
        out[0] = s;
    }
}

extern "C" void kernel_launch(void* const* d_in, const int* in_sizes, int n_in,
                              void* d_out, int out_size) {
    const float* x_inf  = (const float*)d_in[0];
    const float* x_item = (const float*)d_in[1];
    const int*   e1s    = (const int*)d_in[2];
    const int*   e1d    = (const int*)d_in[3];
    const int*   e2s    = (const int*)d_in[4];
    const int*   e2d    = (const int*)d_in[5];
    const int*   tgt    = (const int*)d_in[6];
    const float* W1a_l  = (const float*)d_in[7];
    const float* b1a_l  = (const float*)d_in[8];
    const float* W1a_r  = (const float*)d_in[9];
    const float* W1b_l  = (const float*)d_in[10];
    const float* b1b_l  = (const float*)d_in[11];
    const float* W1b_r  = (const float*)d_in[12];
    // d_in[13..15]: W2a_* (dead code in reference — o_item unused)
    const float* W2b_l  = (const float*)d_in[16];
    const float* b2b_l  = (const float*)d_in[17];
    const float* W2b_r  = (const float*)d_in[18];
    const float* W_ih   = (const float*)d_in[19];
    const float* W_hh   = (const float*)d_in[20];
    const float* b_ih   = (const float*)d_in[21];
    const float* b_hh   = (const float*)d_in[22];
    const float* W_att  = (const float*)d_in[23];
    const float* b_att  = (const float*)d_in[24];
    const float* W_p1   = (const float*)d_in[25];
    const float* b_p1   = (const float*)d_in[26];
    const float* W_p2   = (const float*)d_in[27];
    const float* b_p2   = (const float*)d_in[28];
    float* out = (float*)d_out;

    k_init<<<2048, 256>>>();
    dim3 gscan(512, TT);
    k_scan_e2<<<gscan, 256>>>(e2s, e2d, x_item, tgt);
    k_assign<<<TT, 256>>>();
    k_scan_e1<<<gscan, 256>>>(e1s, e1d, x_inf);
    k_hitem<<<dim3(64, TT), 256>>>(x_item, W1a_l, b1a_l, W1a_r);
    k_oinf<<<TT, 256>>>(x_inf, W1b_l, b1b_l, W1b_r, W2b_l, b2b_l, W2b_r, tgt);
    k_gi<<<dim3(12, TT), 256>>>(W_ih, b_ih);
    for (int t = 0; t < TT; t++)
        k_gru<<<32, 256>>>(t, W_hh, b_hh);
    k_head<<<1, 256>>>(W_att, b_att, W_p1, b_p1, W_p2, b_p2, out);
}

// round 9
// speedup vs baseline: 12.0060x; 1.0347x over previous
#include <cuda_runtime.h>
#include <math.h>

#define TT 8
#define NI 20000
#define NK 50000
#define FF 128
#define HH 256
#define OO 128
#define EE 500000
#define MAXS 512

// ---------------- scratch (device globals; no allocation allowed) ----------------
__device__ int   g_item_flag[TT][NK];     // -1 empty, -2 marked, >=0 slot
__device__ int   g_item_mult[TT][NK];     // edge multiplicity (src,target) in e2
__device__ int   g_item_id[TT][MAXS];
__device__ int   g_item_cnt[TT][MAXS];    // e1 in-degree of needed item
__device__ float g_item_acc[TT][MAXS][FF];
__device__ float g_hitem[TT][MAXS][HH];
__device__ int   g_num_items[TT];
__device__ float g_accx[TT][FF];          // sum of x_item over target's e2 edges
__device__ int   g_edge_cnt[TT];
__device__ float g_seq[TT][OO];
__device__ float g_gi[TT][3 * HH];
__device__ float g_hbuf[2][HH];
__device__ float g_rnn[TT][HH];

// ---------------- init / reset (R1-proven) ----------------
__global__ void k_init() {
    int idx = blockIdx.x * blockDim.x + threadIdx.x;
    if (idx < TT * NK) {
        ((int*)g_item_flag)[idx] = -1;
        ((int*)g_item_mult)[idx] = 0;
    }
    if (idx < TT * MAXS * FF) ((float*)g_item_acc)[idx] = 0.0f;
    if (idx < TT * MAXS)      ((int*)g_item_cnt)[idx] = 0;
    if (idx < TT * FF)        ((float*)g_accx)[idx] = 0.0f;
    if (idx < TT) { g_edge_cnt[idx] = 0; g_num_items[idx] = 0; }
    if (idx < 2 * HH) ((float*)g_hbuf)[idx] = 0.0f;
}

// ---------------- pass A: scan e2, int4 one-shot (4x MLP) ----------------
__device__ __forceinline__ void e2_hit(int t, int e, const int* __restrict__ s,
                                       const float* __restrict__ x_item) {
    int src = s[e];
    atomicAdd(&g_edge_cnt[t], 1);
    atomicAdd(&g_item_mult[t][src], 1);
    int old = atomicExch(&g_item_flag[t][src], -2);
    if (old == -1) {
        int sl = atomicAdd(&g_num_items[t], 1);
        if (sl < MAXS) g_item_id[t][sl] = src;
    }
    const float* xr = x_item + ((size_t)t * NK + src) * FF;
    #pragma unroll 4
    for (int f = 0; f < FF; f++) atomicAdd(&g_accx[t][f], xr[f]);
}

__global__ void k_scan_e2(const int* __restrict__ e2s, const int* __restrict__ e2d,
                          const float* __restrict__ x_item, const int* __restrict__ tgtp) {
    int t = blockIdx.y;
    int i = blockIdx.x * blockDim.x + threadIdx.x;
    if (i >= EE / 4) return;
    int tgt = *tgtp;
    const int4* d4 = (const int4*)(e2d + (size_t)t * EE);
    const int* s = e2s + (size_t)t * EE;
    int4 dv = __ldg(d4 + i);
    int e = 4 * i;
    if (dv.x == tgt) e2_hit(t, e + 0, s, x_item);
    if (dv.y == tgt) e2_hit(t, e + 1, s, x_item);
    if (dv.z == tgt) e2_hit(t, e + 2, s, x_item);
    if (dv.w == tgt) e2_hit(t, e + 3, s, x_item);
}

// ---------------- pass A2: assign slot ids (R1-proven, untouched) ----------------
__global__ void k_assign() {
    int t = blockIdx.x;
    if (threadIdx.x == 0 && g_num_items[t] > MAXS) g_num_items[t] = MAXS;
    __syncthreads();
    int n = g_num_items[t];
    for (int k = threadIdx.x; k < n; k += blockDim.x)
        g_item_flag[t][g_item_id[t][k]] = k;
}

// ---------------- pass B: scan e1, int4 + 4 independent probes ----------------
__device__ __forceinline__ void e1_hit(int t, int sl, int e, const int* __restrict__ s,
                                       const float* __restrict__ x_inf) {
    atomicAdd(&g_item_cnt[t][sl], 1);
    int src = s[e];
    const float* xr = x_inf + ((size_t)t * NI + src) * FF;
    #pragma unroll 4
    for (int f = 0; f < FF; f++) atomicAdd(&g_item_acc[t][sl][f], xr[f]);
}

__global__ void k_scan_e1(const int* __restrict__ e1s, const int* __restrict__ e1d,
                          const float* __restrict__ x_inf) {
    int t = blockIdx.y;
    int i = blockIdx.x * blockDim.x + threadIdx.x;
    if (i >= EE / 4) return;
    const int4* d4 = (const int4*)(e1d + (size_t)t * EE);
    const int* s = e1s + (size_t)t * EE;
    const int* flag = g_item_flag[t];
    int4 dv = __ldg(d4 + i);
    // 4 independent probes in flight before any branch (MLP vs L2 latency)
    int f0 = __ldg(&flag[dv.x]);
    int f1 = __ldg(&flag[dv.y]);
    int f2 = __ldg(&flag[dv.z]);
    int f3 = __ldg(&flag[dv.w]);
    int e = 4 * i;
    if (f0 >= 0) e1_hit(t, f0, e + 0, s, x_inf);
    if (f1 >= 0) e1_hit(t, f1, e + 1, s, x_inf);
    if (f2 >= 0) e1_hit(t, f2, e + 2, s, x_inf);
    if (f3 >= 0) e1_hit(t, f3, e + 3, s, x_inf);
}

__device__ __forceinline__ float warp_sum(float v) {
    #pragma unroll
    for (int off = 16; off > 0; off >>= 1) v += __shfl_down_sync(0xffffffffu, v, off);
    return v;
}

// ---------------- pass C: h_item, COALESCED warp-per-row (R8-proven) ----------------
__global__ void k_hitem(const float* __restrict__ x_item,
                        const float* __restrict__ W1a_l, const float* __restrict__ b1a_l,
                        const float* __restrict__ W1a_r) {
    int t = blockIdx.y;
    int tid = threadIdx.x;
    int wid = tid >> 5, lane = tid & 31;
    __shared__ float4 mean4[FF / 4], xrow4[FF / 4];
    for (int sl = blockIdx.x; sl < g_num_items[t]; sl += gridDim.x) {
        int id = g_item_id[t][sl];
        float c = fmaxf((float)g_item_cnt[t][sl], 1.0f);
        if (tid < FF) {
            ((float*)mean4)[tid] = g_item_acc[t][sl][tid] / c;
            ((float*)xrow4)[tid] = x_item[((size_t)t * NK + id) * FF + tid];
        }
        __syncthreads();
        float4 m = mean4[lane], x = xrow4[lane];
        for (int h = wid; h < HH; h += 8) {
            float4 wl = ((const float4*)(W1a_l + (size_t)h * FF))[lane];
            float4 wr = ((const float4*)(W1a_r + (size_t)h * FF))[lane];
            float a = wl.x * m.x + wl.y * m.y + wl.z * m.z + wl.w * m.w
                    + wr.x * x.x + wr.y * x.y + wr.z * x.z + wr.w * x.w;
            a = warp_sum(a);
            if (lane == 0) g_hitem[t][sl][h] = fmaxf(a + b1a_l[h], 0.0f);
        }
        __syncthreads();
    }
}

// ---------------- pass D: h_inf[target] + o_inf[target], COALESCED (R8-proven) ----------------
__global__ void k_oinf(const float* __restrict__ x_inf,
                       const float* __restrict__ W1b_l, const float* __restrict__ b1b_l,
                       const float* __restrict__ W1b_r,
                       const float* __restrict__ W2b_l, const float* __restrict__ b2b_l,
                       const float* __restrict__ W2b_r,
                       const int* __restrict__ tgtp) {
    int t = blockIdx.x;
    int tid = threadIdx.x;
    int wid = tid >> 5, lane = tid & 31;
    int tgt = *tgtp;
    __shared__ float4 meanx4[FF / 4], xt4[FF / 4];
    __shared__ float4 hinf4[HH / 4], meanh4[HH / 4];
    __shared__ float multw[MAXS];
    float ec = fmaxf((float)g_edge_cnt[t], 1.0f);
    int n = g_num_items[t];
    if (n > MAXS) n = MAXS;
    if (tid < FF) {
        ((float*)meanx4)[tid] = g_accx[t][tid] / ec;
        ((float*)xt4)[tid]    = x_inf[((size_t)t * NI + tgt) * FF + tid];
    }
    for (int k = tid; k < n; k += blockDim.x)
        multw[k] = (float)g_item_mult[t][g_item_id[t][k]];
    __syncthreads();

    {
        float mh = 0.0f;
        for (int k = 0; k < n; k++) mh += multw[k] * g_hitem[t][k][tid];
        ((float*)meanh4)[tid] = mh / ec;
    }
    {
        float4 m = meanx4[lane], x = xt4[lane];
        for (int h = wid; h < HH; h += 8) {
            float4 wl = ((const float4*)(W1b_l + (size_t)h * FF))[lane];
            float4 wr = ((const float4*)(W1b_r + (size_t)h * FF))[lane];
            float a = wl.x * m.x + wl.y * m.y + wl.z * m.z + wl.w * m.w
                    + wr.x * x.x + wr.y * x.y + wr.z * x.z + wr.w * x.w;
            a = warp_sum(a);
            if (lane == 0) ((float*)hinf4)[h] = fmaxf(a + b1b_l[h], 0.0f);
        }
    }
    __syncthreads();

    {
        float4 m0 = meanh4[lane], m1 = meanh4[lane + 32];
        float4 h0 = hinf4[lane],  h1 = hinf4[lane + 32];
        for (int o = wid; o < OO; o += 8) {
            const float4* wl = (const float4*)(W2b_l + (size_t)o * HH);
            const float4* wr = (const float4*)(W2b_r + (size_t)o * HH);
            float4 a0 = wl[lane], a1 = wl[lane + 32];
            float4 b0 = wr[lane], b1 = wr[lane + 32];
            float v = a0.x * m0.x + a0.y * m0.y + a0.z * m0.z + a0.w * m0.w
                    + a1.x * m1.x + a1.y * m1.y + a1.z * m1.z + a1.w * m1.w
                    + b0.x * h0.x + b0.y * h0.y + b0.z * h0.z + b0.w * h0.w
                    + b1.x * h1.x + b1.y * h1.y + b1.z * h1.z + b1.w * h1.w;
            v = warp_sum(v);
            if (lane == 0) g_seq[t][o] = v + b2b_l[o];
        }
    }
}

// ---------------- GRU input gates, COALESCED warp-per-row (R8-proven) ----------------
__global__ void k_gi(const float* __restrict__ W_ih, const float* __restrict__ b_ih) {
    int t = blockIdx.y;
    int tid = threadIdx.x;
    int wid = tid >> 5, lane = tid & 31;
    __shared__ float4 xs4[OO / 4];
    if (tid < OO) ((float*)xs4)[tid] = g_seq[t][tid];
    __syncthreads();
    float4 x = xs4[lane];
    int gw = blockIdx.x * 8 + wid;           // 0..95 global warps
    for (int row = gw; row < 3 * HH; row += 96) {
        float4 w = ((const float4*)(W_ih + (size_t)row * OO))[lane];
        float v = w.x * x.x + w.y * x.y + w.z * x.z + w.w * x.w;
        v = warp_sum(v);
        if (lane == 0) g_gi[t][row] = v + b_ih[row];
    }
}

// ---------------- one GRU step: warp per h-row (R1-proven, untouched) ----------------
__global__ void k_gru(int t, const float* __restrict__ W_hh, const float* __restrict__ b_hh) {
    const float* hprev = g_hbuf[t & 1];
    float* hnext = g_hbuf[(t + 1) & 1];
    int gwarp = (blockIdx.x * blockDim.x + threadIdx.x) >> 5;
    int lane = threadIdx.x & 31;
    if (gwarp >= HH) return;
    int w = gwarp;
    float sr = 0.0f, sz = 0.0f, sn = 0.0f;
    const float* wr = W_hh + (size_t)w * HH;
    const float* wz = W_hh + (size_t)(HH + w) * HH;
    const float* wn = W_hh + (size_t)(2 * HH + w) * HH;
    #pragma unroll
    for (int j = 0; j < HH / 32; j++) {
        int k = lane + 32 * j;
        float hv = hprev[k];
        sr += wr[k] * hv;
        sz += wz[k] * hv;
        sn += wn[k] * hv;
    }
    #pragma unroll
    for (int off = 16; off > 0; off >>= 1) {
        sr += __shfl_down_sync(0xffffffffu, sr, off);
        sz += __shfl_down_sync(0xffffffffu, sz, off);
        sn += __shfl_down_sync(0xffffffffu, sn, off);
    }
    if (lane == 0) {
        float gh_r = sr + b_hh[w];
        float gh_z = sz + b_hh[HH + w];
        float gh_n = sn + b_hh[2 * HH + w];
        float gi_r = g_gi[t][w];
        float gi_z = g_gi[t][HH + w];
        float gi_n = g_gi[t][2 * HH + w];
        float r = 1.0f / (1.0f + expf(-(gi_r + gh_r)));
        float z = 1.0f / (1.0f + expf(-(gi_z + gh_z)));
        float nn = tanhf(gi_n + r * gh_n);
        float hn = (1.0f - z) * nn + z * hprev[w];
        hnext[w] = hn;
        g_rnn[t][w] = hn;
    }
}

// ---------------- attention + prediction head (R1-proven, untouched) ----------------
__global__ void k_head(const float* __restrict__ W_att, const float* __restrict__ b_att,
                       const float* __restrict__ W_p1, const float* __restrict__ b_p1,
                       const float* __restrict__ W_p2, const float* __restrict__ b_p2,
                       float* __restrict__ out) {
    __shared__ float att[TT], ctx[HH], red[HH];
    int tid = threadIdx.x;
    if (tid < TT) {
        float lg = b_att[0];
        for (int h = 0; h < HH; h++) lg += g_rnn[tid][h] * W_att[h];
        att[tid] = lg;
    }
    __syncthreads();
    if (tid == 0) {
        float m = att[0];
        for (int t = 1; t < TT; t++) m = fmaxf(m, att[t]);
        float s = 0.0f;
        for (int t = 0; t < TT; t++) { att[t] = expf(att[t] - m); s += att[t]; }
        for (int t = 0; t < TT; t++) att[t] /= s;
    }
    __syncthreads();
    {
        float c = 0.0f;
        #pragma unroll
        for (int t = 0; t < TT; t++) c += att[t] * g_rnn[t][tid];
        ctx[tid] = c;
    }
    __syncthreads();
    if (tid < HH / 2) {
        float v = b_p1[tid];
        const float* w = W_p1 + (size_t)tid * HH;
        #pragma unroll 8
        for (int h = 0; h < HH; h++) v += w[h] * ctx[h];
        v = fmaxf(v, 0.0f);
        red[tid] = v * W_p2[tid];
    }
    __syncthreads();
    if (tid == 0) {
        float s = b_p2[0];
        for (int j = 0; j < HH / 2; j++) s += red[j];
        out[0] = s;
    }
}

extern "C" void kernel_launch(void* const* d_in, const int* in_sizes, int n_in,
                              void* d_out, int out_size) {
    const float* x_inf  = (const float*)d_in[0];
    const float* x_item = (const float*)d_in[1];
    const int*   e1s    = (const int*)d_in[2];
    const int*   e1d    = (const int*)d_in[3];
    const int*   e2s    = (const int*)d_in[4];
    const int*   e2d    = (const int*)d_in[5];
    const int*   tgt    = (const int*)d_in[6];
    const float* W1a_l  = (const float*)d_in[7];
    const float* b1a_l  = (const float*)d_in[8];
    const float* W1a_r  = (const float*)d_in[9];
    const float* W1b_l  = (const float*)d_in[10];
    const float* b1b_l  = (const float*)d_in[11];
    const float* W1b_r  = (const float*)d_in[12];
    // d_in[13..15]: W2a_* (dead code in reference — o_item unused)
    const float* W2b_l  = (const float*)d_in[16];
    const float* b2b_l  = (const float*)d_in[17];
    const float* W2b_r  = (const float*)d_in[18];
    const float* W_ih   = (const float*)d_in[19];
    const float* W_hh   = (const float*)d_in[20];
    const float* b_ih   = (const float*)d_in[21];
    const float* b_hh   = (const float*)d_in[22];
    const float* W_att  = (const float*)d_in[23];
    const float* b_att  = (const float*)d_in[24];
    const float* W_p1   = (const float*)d_in[25];
    const float* b_p1   = (const float*)d_in[26];
    const float* W_p2   = (const float*)d_in[27];
    const float* b_p2   = (const float*)d_in[28];
    float* out = (float*)d_out;

    k_init<<<2048, 256>>>();
    dim3 gscan((EE / 4 + 255) / 256, TT);
    k_scan_e2<<<gscan, 256>>>(e2s, e2d, x_item, tgt);
    k_assign<<<TT, 256>>>();
    k_scan_e1<<<gscan, 256>>>(e1s, e1d, x_inf);
    k_hitem<<<dim3(64, TT), 256>>>(x_item, W1a_l, b1a_l, W1a_r);
    k_oinf<<<TT, 256>>>(x_inf, W1b_l, b1b_l, W1b_r, W2b_l, b2b_l, W2b_r, tgt);
    k_gi<<<dim3(12, TT), 256>>>(W_ih, b_ih);
    for (int t = 0; t < TT; t++)
        k_gru<<<32, 256>>>(t, W_hh, b_hh);
    k_head<<<1, 256>>>(W_att, b_att, W_p1, b_p1, W_p2, b_p2, out);
}